// round 11
// baseline (speedup 1.0000x reference)
#include <cuda_runtime.h>
#include <cuda_fp16.h>
#include <cstdint>
#include <cstddef>

// Problem constants
#define BB   8
#define SS_  4096
#define DD   1024
#define PP   2051
#define KK   1024
#define MM   (BB*SS_)       // 32768
#define N1PAD 2304          // GEMM1 N padded to 9*256

// ---------------- scratch (device globals; no allocation allowed) ------------
__device__ __half g_Ah [(size_t)MM*KK];     // input as fp16
__device__ __half g_B1h[(size_t)N1PAD*KK];  // W_in^T  [n][k] fp16, zero-padded
__device__ __half g_B2h[(size_t)DD*KK];     // W_ctx   [n][k] fp16 (no transpose)
__device__ __half g_B3h[(size_t)DD*KK];     // W_out^T [n][k] fp16
__device__ __half g_cah[(size_t)MM*DD];     // context_all as fp16 (GEMM2 A)
__device__ __half g_yh [(size_t)MM*DD];     // y as fp16 (GEMM3 A)
__device__ float g_query[(size_t)MM*DD];
__device__ float g_ctx  [(size_t)MM*DD];
__device__ float g_gates[(size_t)MM*3];
__device__ float g_ca   [(size_t)MM*DD];
__device__ float g_c1part[(size_t)BB*DD*32];
__device__ float g_g    [(size_t)BB*DD];

// ---------------- helpers ----------------------------------------------------
__device__ __forceinline__ float gelu_f(float x) {
    return 0.5f * x * (1.0f + erff(x * 0.70710678118654752440f));
}
__device__ __forceinline__ void cp16(uint32_t dst, const void* src) {
    asm volatile("cp.async.cg.shared.global [%0], [%1], 16;" :: "r"(dst), "l"(src));
}
#define LDSM4(R, addr) asm volatile( \
    "ldmatrix.sync.aligned.m8n8.x4.shared.b16 {%0,%1,%2,%3}, [%4];" \
    : "=r"((R)[0]), "=r"((R)[1]), "=r"((R)[2]), "=r"((R)[3]) : "r"(addr))

__device__ __forceinline__ void mma16(float* c, const uint32_t* a,
                                      uint32_t b0, uint32_t b1) {
    asm volatile(
        "mma.sync.aligned.m16n8k16.row.col.f32.f16.f16.f32 "
        "{%0,%1,%2,%3}, {%4,%5,%6,%7}, {%8,%9}, {%0,%1,%2,%3};"
        : "+f"(c[0]), "+f"(c[1]), "+f"(c[2]), "+f"(c[3])
        : "r"(a[0]), "r"(a[1]), "r"(a[2]), "r"(a[3]), "r"(b0), "r"(b1));
}

// ---------------- prep kernels -----------------------------------------------
__global__ void cvtA_kernel(const float* __restrict__ x, int n4) {
    int i = blockIdx.x * blockDim.x + threadIdx.x;
    if (i >= n4) return;
    float4 v = ((const float4*)x)[i];
    ((__half2*)g_Ah)[2 * (size_t)i]     = __floats2half2_rn(v.x, v.y);
    ((__half2*)g_Ah)[2 * (size_t)i + 1] = __floats2half2_rn(v.z, v.w);
}
// B1h[n][k] = half(W_in[k][n]), n<PP else 0. grid (72,32) block (32,8)
__global__ void prep_b1h_kernel(const float* __restrict__ W) {
    __shared__ float t[32][33];
    const int n0 = blockIdx.x << 5, k0 = blockIdx.y << 5;
    const int tx = threadIdx.x, ty = threadIdx.y;
#pragma unroll
    for (int j = 0; j < 32; j += 8) {
        int n = n0 + tx;
        t[ty + j][tx] = (n < PP) ? W[(size_t)(k0 + ty + j) * PP + n] : 0.0f;
    }
    __syncthreads();
#pragma unroll
    for (int j = 0; j < 32; j += 8)
        g_B1h[(size_t)(n0 + ty + j) * KK + k0 + tx] = __float2half_rn(t[tx][ty + j]);
}
// B2h = half(W_ctx) elementwise (W_ctx is [o][c] = [n][k] already)
__global__ void prep_b2h_kernel(const float* __restrict__ W, int n4) {
    int i = blockIdx.x * blockDim.x + threadIdx.x;
    if (i >= n4) return;
    float4 v = ((const float4*)W)[i];
    ((__half2*)g_B2h)[2 * (size_t)i]     = __floats2half2_rn(v.x, v.y);
    ((__half2*)g_B2h)[2 * (size_t)i + 1] = __floats2half2_rn(v.z, v.w);
}
// B3h[n][k] = half(W_out[k][n]). grid (32,32) block (32,8)
__global__ void prep_b3h_kernel(const float* __restrict__ W) {
    __shared__ float t[32][33];
    const int n0 = blockIdx.x << 5, k0 = blockIdx.y << 5;
    const int tx = threadIdx.x, ty = threadIdx.y;
#pragma unroll
    for (int j = 0; j < 32; j += 8)
        t[ty + j][tx] = W[(size_t)(k0 + ty + j) * DD + n0 + tx];
    __syncthreads();
#pragma unroll
    for (int j = 0; j < 32; j += 8)
        g_B3h[(size_t)(n0 + ty + j) * KK + k0 + tx] = __float2half_rn(t[tx][ty + j]);
}

// ------- fp16 mma.sync GEMM: 128x256 CTA tile, 512 thr, kt=64, 4 stages ------
// Warp grid 4(M) x 4(N); each warp: 32 rows x 64 cols (2 mi x 8 ni frags).
// MODE 0: proj = Ah @ B1h^T + b_in -> split query/ctx/gates (fp32)
// MODE 1: y = (cah @ B2h^T + b_ctx) * query -> g_yh (fp16)
// MODE 2: out = yh @ B3h^T + b_out -> Cout (fp32)
#define STAGE_BYTES 49152u   // A 16KB + B 32KB
template <int MODE>
__global__ void __launch_bounds__(512, 1)
gemm_fp16(const __half* __restrict__ A, const __half* __restrict__ Bm,
          const float* __restrict__ bias, float* __restrict__ Cout) {
    extern __shared__ __align__(128) char smem[];
    uint32_t sbase;
    asm("{\n\t.reg .u64 t;\n\tcvta.to.shared.u64 t, %1;\n\tcvt.u32.u64 %0, t;\n\t}"
        : "=r"(sbase) : "l"(smem));

    const int tid  = threadIdx.x;
    const int lane = tid & 31;
    const int warp = tid >> 5;
    const int wm   = warp & 3;    // 4 warps over M (32 rows each)
    const int wn   = warp >> 2;   // 4 warps over N (64 cols each)
    const int m0   = blockIdx.y << 7;
    const int n0   = blockIdx.x << 8;

    float acc[2][8][4];
#pragma unroll
    for (int i = 0; i < 2; i++)
#pragma unroll
        for (int j = 0; j < 8; j++)
#pragma unroll
            for (int k = 0; k < 4; k++) acc[i][j][k] = 0.0f;

    // ldmatrix lane geometry (SW128: chunk ^= row&7)
    const uint32_t sw   = (uint32_t)(lane & 7) << 4;
    const uint32_t aK16 = ((lane >> 4) & 1) * 16;           // A: mats 2,3 -> k+8
    const uint32_t bK16 = ((lane >> 3) & 1) * 16;           // B: mats 1,3 -> k+8
    const int aRowL = (lane & 15);
    const int bRowL = (lane & 7) + ((lane >> 4) & 1) * 8;
    uint32_t aOff[2], bOff[4];
#pragma unroll
    for (int mi = 0; mi < 2; mi++)
        aOff[mi] = (uint32_t)(wm * 32 + mi * 16 + aRowL) * 128;
#pragma unroll
    for (int g = 0; g < 4; g++)
        bOff[g] = (uint32_t)(wn * 64 + g * 16 + bRowL) * 128;

    auto load_stage = [&](int kt, int s) {
        const int k0 = kt << 6;
        const uint32_t sA = sbase + (uint32_t)s * STAGE_BYTES;
        const uint32_t sB = sA + 16384u;
#pragma unroll
        for (int i = 0; i < 2; i++) {                 // A: 128 rows x 8 chunks
            const int idx = tid + i * 512;
            const int row = idx >> 3, c = idx & 7;
            cp16(sA + (uint32_t)(row * 128) + (uint32_t)((c ^ (row & 7)) << 4),
                 A + (size_t)(m0 + row) * KK + k0 + c * 8);
        }
#pragma unroll
        for (int i = 0; i < 4; i++) {                 // B: 256 rows x 8 chunks
            const int idx = tid + i * 512;
            const int row = idx >> 3, c = idx & 7;
            cp16(sB + (uint32_t)(row * 128) + (uint32_t)((c ^ (row & 7)) << 4),
                 Bm + (size_t)(n0 + row) * KK + k0 + c * 8);
        }
        asm volatile("cp.async.commit_group;");
    };

    // 4-stage prologue: chunks 0,1,2 in flight
    load_stage(0, 0);
    load_stage(1, 1);
    load_stage(2, 2);

    for (int kt = 0; kt < 16; ++kt) {
        // retire chunk kt (issued 3 iterations ahead)
        if (kt <= 13)      asm volatile("cp.async.wait_group 2;");
        else if (kt == 14) asm volatile("cp.async.wait_group 1;");
        else               asm volatile("cp.async.wait_group 0;");
        __syncthreads();   // stage kt%4 ready; stage (kt+3)%4 reads (iter kt-1) done

        if (kt + 3 < 16) load_stage(kt + 3, (kt + 3) & 3);

        const uint32_t sA = sbase + (uint32_t)(kt & 3) * STAGE_BYTES;
        const uint32_t sB = sA + 16384u;
#pragma unroll
        for (int kk = 0; kk < 4; ++kk) {
            uint32_t a[2][4], b[4][4];
#pragma unroll
            for (int mi = 0; mi < 2; mi++)
                LDSM4(a[mi], sA + aOff[mi] + (((uint32_t)(kk * 32) + aK16) ^ sw));
#pragma unroll
            for (int g = 0; g < 4; g++)
                LDSM4(b[g], sB + bOff[g] + (((uint32_t)(kk * 32) + bK16) ^ sw));
#pragma unroll
            for (int mi = 0; mi < 2; mi++)
#pragma unroll
                for (int ni = 0; ni < 8; ni++)
                    mma16(acc[mi][ni], a[mi],
                          b[ni >> 1][(ni & 1) * 2], b[ni >> 1][(ni & 1) * 2 + 1]);
        }
    }

    // epilogue (direct stores)
    const int r  = lane >> 2;
    const int cq = lane & 3;
#pragma unroll
    for (int mi = 0; mi < 2; mi++) {
#pragma unroll
        for (int ni = 0; ni < 8; ni++) {
#pragma unroll
            for (int cr = 0; cr < 4; cr++) {
                const int row = m0 + wm * 32 + mi * 16 + r + ((cr >> 1) << 3);
                const int col = n0 + wn * 64 + ni * 8 + (cq << 1) + (cr & 1);
                float v = acc[mi][ni][cr];
                if (MODE == 0) {
                    if (col < PP) {
                        v += __ldg(bias + col);
                        if (col < DD)
                            g_query[(size_t)row * DD + col] = v;
                        else if (col < 2 * DD)
                            g_ctx[(size_t)row * DD + (col - DD)] = v;
                        else
                            g_gates[(size_t)row * 3 + (col - 2 * DD)] = v;
                    }
                } else if (MODE == 1) {
                    v += __ldg(bias + col);
                    v *= __ldg(&g_query[(size_t)row * DD + col]);
                    g_yh[(size_t)row * DD + col] = __float2half_rn(v);
                } else {
                    v += __ldg(bias + col);
                    Cout[(size_t)row * DD + col] = v;
                }
            }
        }
    }
}

// ---------------- depthwise conv chain (k=14 then k=18) ----------------------
// Register sliding-window: contiguous run of outputs per thread.
__global__ void __launch_bounds__(256)
conv_kernel(const float* __restrict__ w0p, const float* __restrict__ b0p,
            const float* __restrict__ w1p, const float* __restrict__ b1p) {
    __shared__ float xs[158 * 32];   // ctx tile: s = s0-14 .. s0+143
    __shared__ float c0s[146 * 32];  // c0 tile:  u = s0-8  .. s0+136

    const int tid = threadIdx.x;
    const int d = tid & 31, chunk = tid >> 5;
    const int b = blockIdx.z, d0 = blockIdx.y << 5, s0 = blockIdx.x << 7;
    const int dg = d0 + d;

    float W0[14], W1[18];
#pragma unroll
    for (int i = 0; i < 14; i++) W0[i] = __ldg(w0p + dg * 14 + i);
#pragma unroll
    for (int i = 0; i < 18; i++) W1[i] = __ldg(w1p + dg * 18 + i);
    const float B0 = __ldg(b0p + dg);
    const float B1 = __ldg(b1p + dg);

    {
        const float* ctxb = g_ctx + (size_t)b * SS_ * DD + d0;
        for (int idx = tid; idx < 158 * 8; idx += 256) {
            const int sl = idx >> 3, q = idx & 7;
            const int s = s0 - 14 + sl;
            float4 v = make_float4(0.f, 0.f, 0.f, 0.f);
            if (s >= 0 && s < SS_)
                v = *(const float4*)(ctxb + (size_t)s * DD + q * 4);
            *(float4*)(&xs[sl * 32 + q * 4]) = v;
        }
    }
    __syncthreads();

    // c0 phase: 145 outputs, contiguous runs of 19/thread
    {
        const int ul0 = chunk * 19;
        const int cnt = min(19, 145 - ul0);
        float w[14];
#pragma unroll
        for (int j = 0; j < 14; j++) w[j] = xs[(ul0 + j) * 32 + d];
#pragma unroll
        for (int it = 0; it < 19; ++it) {
            if (it < cnt) {
                float a = B0;
#pragma unroll
                for (int i = 0; i < 14; i++) a += w[(it + i) % 14] * W0[i];
                const int u = s0 - 8 + ul0 + it;
                c0s[(ul0 + it) * 32 + d] = (u >= 0 && u < SS_) ? gelu_f(a) : 0.0f;
                if (it + 1 < cnt)
                    w[it % 14] = xs[(ul0 + it + 14) * 32 + d];
            }
        }
    }
    __syncthreads();

    // c1 phase: 128 outputs, contiguous runs of 16/thread
    float csum = 0.0f;
    {
        const int tl0 = chunk * 16;
        float w[18];
#pragma unroll
        for (int j = 0; j < 18; j++) w[j] = c0s[(tl0 + j) * 32 + d];
#pragma unroll
        for (int it = 0; it < 16; ++it) {
            float a = B1;
#pragma unroll
            for (int i = 0; i < 18; i++) a += w[(it + i) % 18] * W1[i];
            const float c1 = gelu_f(a);
            csum += c1;
            const int t = s0 + tl0 + it;
            const size_t ms = (size_t)b * SS_ + t;
            const float g0v = __ldg(&g_gates[ms * 3 + 0]);
            const float g1v = __ldg(&g_gates[ms * 3 + 1]);
            const float c0c = w[(it + 8) % 18];
            g_ca[ms * DD + dg] = c0c * g0v + c1 * g1v;
            if (it + 1 < 16)
                w[it % 18] = c0s[(tl0 + it + 18) * 32 + d];
        }
    }
    __syncthreads();
    xs[chunk * 32 + d] = csum;
    __syncthreads();
    if (chunk == 0) {
        float s_ = 0.0f;
#pragma unroll
        for (int j = 0; j < 8; j++) s_ += xs[j * 32 + d];
        g_c1part[((size_t)b * DD + dg) * 32 + blockIdx.x] = s_;
    }
}

__global__ void gmean_kernel() {
    const int i = blockIdx.x * blockDim.x + threadIdx.x;
    if (i < BB * DD) {
        float s = 0.0f;
        const float* p = &g_c1part[(size_t)i * 32];
#pragma unroll
        for (int j = 0; j < 32; j++) s += p[j];
        g_g[i] = gelu_f(s * (1.0f / 4096.0f));
    }
}

// cah = half(ca + g*gates2)
__global__ void finalize_kernel() {
    const size_t i = (size_t)blockIdx.x * blockDim.x + threadIdx.x;
    const int d4 = (int)(i & 255);
    const size_t ms = i >> 8;
    const int b = (int)(ms >> 12);
    const float g2 = __ldg(&g_gates[ms * 3 + 2]);
    const float4 gv = ((const float4*)g_g)[(size_t)b * 256 + d4];
    float4 c = ((const float4*)g_ca)[i];
    c.x = fmaf(gv.x, g2, c.x);
    c.y = fmaf(gv.y, g2, c.y);
    c.z = fmaf(gv.z, g2, c.z);
    c.w = fmaf(gv.w, g2, c.w);
    ((__half2*)g_cah)[2 * i]     = __floats2half2_rn(c.x, c.y);
    ((__half2*)g_cah)[2 * i + 1] = __floats2half2_rn(c.z, c.w);
}

// ---------------- launch -----------------------------------------------------
extern "C" void kernel_launch(void* const* d_in, const int* in_sizes, int n_in,
                              void* d_out, int out_size) {
    (void)in_sizes; (void)n_in; (void)out_size;
    const float* input = (const float*)d_in[0];
    const float* W_in  = (const float*)d_in[1];
    const float* b_in  = (const float*)d_in[2];
    const float* w0    = (const float*)d_in[3];
    const float* b0    = (const float*)d_in[4];
    const float* w1    = (const float*)d_in[5];
    const float* b1    = (const float*)d_in[6];
    const float* W_ctx = (const float*)d_in[7];
    const float* b_ctx = (const float*)d_in[8];
    const float* W_out = (const float*)d_in[9];
    const float* b_out = (const float*)d_in[10];
    float* out = (float*)d_out;

    void *pAh = nullptr, *pB1 = nullptr, *pB2 = nullptr, *pB3 = nullptr,
         *pCa = nullptr, *pY = nullptr;
    cudaGetSymbolAddress(&pAh, g_Ah);
    cudaGetSymbolAddress(&pB1, g_B1h);
    cudaGetSymbolAddress(&pB2, g_B2h);
    cudaGetSymbolAddress(&pB3, g_B3h);
    cudaGetSymbolAddress(&pCa, g_cah);
    cudaGetSymbolAddress(&pY, g_yh);

    const int GSMEM = 4 * 49152;   // 192KB: 4 stages x (16KB A + 32KB B)
    cudaFuncSetAttribute(gemm_fp16<0>, cudaFuncAttributeMaxDynamicSharedMemorySize, GSMEM);
    cudaFuncSetAttribute(gemm_fp16<1>, cudaFuncAttributeMaxDynamicSharedMemorySize, GSMEM);
    cudaFuncSetAttribute(gemm_fp16<2>, cudaFuncAttributeMaxDynamicSharedMemorySize, GSMEM);

    // 0-2: operand prep needed by GEMM1
    cvtA_kernel<<<(MM * KK / 4 + 255) / 256, 256>>>(input, MM * KK / 4);
    prep_b1h_kernel<<<dim3(72, 32), dim3(32, 8)>>>(W_in);
    prep_b2h_kernel<<<(DD * KK / 4 + 255) / 256, 256>>>(W_ctx, DD * KK / 4);
    // 3: GEMM1
    gemm_fp16<0><<<dim3(9, 256), 512, GSMEM>>>((const __half*)pAh, (const __half*)pB1,
                                               b_in, nullptr);
    // 4: remaining prep
    prep_b3h_kernel<<<dim3(32, 32), dim3(32, 8)>>>(W_out);
    // 5: conv chain -> ca + c1 partial sums
    conv_kernel<<<dim3(32, 32, 8), 256>>>(w0, b0, w1, b1);
    // 6: g = gelu(mean c1)
    gmean_kernel<<<32, 256>>>();
    // 7: cah = half(ca + g*gates2)
    finalize_kernel<<<32768, 256>>>();
    // 8: GEMM2: yh = half((cah @ W_ctx^T + b_ctx) * query)
    gemm_fp16<1><<<dim3(4, 256), 512, GSMEM>>>((const __half*)pCa, (const __half*)pB2,
                                               b_ctx, nullptr);
    // 9: GEMM3: out = yh @ W_out + b_out
    gemm_fp16<2><<<dim3(4, 256), 512, GSMEM>>>((const __half*)pY, (const __half*)pB3,
                                               b_out, out);
}

// round 14
// speedup vs baseline: 1.1057x; 1.1057x over previous
#include <cuda_runtime.h>
#include <cuda_fp16.h>
#include <cstdint>
#include <cstddef>

// Problem constants
#define BB   8
#define SS_  4096
#define DD   1024
#define PP   2051
#define KK   1024
#define MM   (BB*SS_)       // 32768
#define N1PAD 2176          // GEMM1 N padded to 17*128

// ---------------- scratch (device globals; no allocation allowed) ------------
__device__ __half g_Ah [(size_t)MM*KK];     // input as fp16
__device__ __half g_B1h[(size_t)N1PAD*KK];  // W_in^T  [n][k] fp16, zero-padded
__device__ __half g_B2h[(size_t)DD*KK];     // W_ctx   [n][k] fp16 (no transpose)
__device__ __half g_B3h[(size_t)DD*KK];     // W_out^T [n][k] fp16
__device__ __half g_cah[(size_t)MM*DD];     // context_all as fp16 (GEMM2 A)
__device__ __half g_yh [(size_t)MM*DD];     // y as fp16 (GEMM3 A)
__device__ float g_query[(size_t)MM*DD];
__device__ float g_ctx  [(size_t)MM*DD];
__device__ float g_gates[(size_t)MM*3];
__device__ float g_ca   [(size_t)MM*DD];
__device__ float g_c1part[(size_t)BB*DD*32];
__device__ float g_g    [(size_t)BB*DD];

// ---------------- helpers ----------------------------------------------------
__device__ __forceinline__ float gelu_f(float x) {
    return 0.5f * x * (1.0f + erff(x * 0.70710678118654752440f));
}
__device__ __forceinline__ void cp16(uint32_t dst, const void* src) {
    asm volatile("cp.async.cg.shared.global [%0], [%1], 16;" :: "r"(dst), "l"(src));
}
#define LDSM4(R, addr) asm volatile( \
    "ldmatrix.sync.aligned.m8n8.x4.shared.b16 {%0,%1,%2,%3}, [%4];" \
    : "=r"((R)[0]), "=r"((R)[1]), "=r"((R)[2]), "=r"((R)[3]) : "r"(addr))

__device__ __forceinline__ void mma16(float* c, const uint32_t* a,
                                      uint32_t b0, uint32_t b1) {
    asm volatile(
        "mma.sync.aligned.m16n8k16.row.col.f32.f16.f16.f32 "
        "{%0,%1,%2,%3}, {%4,%5,%6,%7}, {%8,%9}, {%0,%1,%2,%3};"
        : "+f"(c[0]), "+f"(c[1]), "+f"(c[2]), "+f"(c[3])
        : "r"(a[0]), "r"(a[1]), "r"(a[2]), "r"(a[3]), "r"(b0), "r"(b1));
}

// ---------------- prep kernels -----------------------------------------------
__global__ void cvtA_kernel(const float* __restrict__ x, int n4) {
    int i = blockIdx.x * blockDim.x + threadIdx.x;
    if (i >= n4) return;
    float4 v = ((const float4*)x)[i];
    ((__half2*)g_Ah)[2 * (size_t)i]     = __floats2half2_rn(v.x, v.y);
    ((__half2*)g_Ah)[2 * (size_t)i + 1] = __floats2half2_rn(v.z, v.w);
}
// B1h[n][k] = half(W_in[k][n]), n<PP else 0. grid (68,32) block (32,8)
__global__ void prep_b1h_kernel(const float* __restrict__ W) {
    __shared__ float t[32][33];
    const int n0 = blockIdx.x << 5, k0 = blockIdx.y << 5;
    const int tx = threadIdx.x, ty = threadIdx.y;
#pragma unroll
    for (int j = 0; j < 32; j += 8) {
        int n = n0 + tx;
        t[ty + j][tx] = (n < PP) ? W[(size_t)(k0 + ty + j) * PP + n] : 0.0f;
    }
    __syncthreads();
#pragma unroll
    for (int j = 0; j < 32; j += 8)
        g_B1h[(size_t)(n0 + ty + j) * KK + k0 + tx] = __float2half_rn(t[tx][ty + j]);
}
// B2h = half(W_ctx) elementwise (W_ctx is [o][c] = [n][k] already)
__global__ void prep_b2h_kernel(const float* __restrict__ W, int n4) {
    int i = blockIdx.x * blockDim.x + threadIdx.x;
    if (i >= n4) return;
    float4 v = ((const float4*)W)[i];
    ((__half2*)g_B2h)[2 * (size_t)i]     = __floats2half2_rn(v.x, v.y);
    ((__half2*)g_B2h)[2 * (size_t)i + 1] = __floats2half2_rn(v.z, v.w);
}
// B3h[n][k] = half(W_out[k][n]). grid (32,32) block (32,8)
__global__ void prep_b3h_kernel(const float* __restrict__ W) {
    __shared__ float t[32][33];
    const int n0 = blockIdx.x << 5, k0 = blockIdx.y << 5;
    const int tx = threadIdx.x, ty = threadIdx.y;
#pragma unroll
    for (int j = 0; j < 32; j += 8)
        t[ty + j][tx] = W[(size_t)(k0 + ty + j) * DD + n0 + tx];
    __syncthreads();
#pragma unroll
    for (int j = 0; j < 32; j += 8)
        g_B3h[(size_t)(n0 + ty + j) * KK + k0 + tx] = __float2half_rn(t[tx][ty + j]);
}

// ---- fp16 mma.sync GEMM: 128x128 tile, kt=64, double buffer (R7 schedule) ---
// MODE 0: proj = Ah @ B1h^T + b_in -> split query/ctx/gates (fp32)
// MODE 1: y = (cah @ B2h^T + b_ctx) * query -> g_yh (fp16)
// MODE 2: out = yh @ B3h^T + b_out -> Cout (fp32)
template <int MODE>
__global__ void __launch_bounds__(256, 2)
gemm_fp16(const __half* __restrict__ A, const __half* __restrict__ Bm,
          const float* __restrict__ bias, float* __restrict__ Cout) {
    extern __shared__ __align__(128) char smem[];
    uint32_t sbase;
    asm("{\n\t.reg .u64 t;\n\tcvta.to.shared.u64 t, %1;\n\tcvt.u32.u64 %0, t;\n\t}"
        : "=r"(sbase) : "l"(smem));

    const int tid  = threadIdx.x;
    const int lane = tid & 31;
    const int warp = tid >> 5;
    const int wm   = warp & 3;    // 4 warps over M (32 rows each)
    const int wn   = warp >> 2;   // 2 warps over N (64 cols each)
    const int m0   = blockIdx.y << 7;
    const int n0   = blockIdx.x << 7;

    float acc[2][8][4];
#pragma unroll
    for (int i = 0; i < 2; i++)
#pragma unroll
        for (int j = 0; j < 8; j++)
#pragma unroll
            for (int k = 0; k < 4; k++) acc[i][j][k] = 0.0f;

    // ldmatrix lane geometry (SW128: chunk ^= row&7, one sw per lane)
    const uint32_t sw   = (uint32_t)(lane & 7) << 4;
    const uint32_t aK16 = ((lane >> 4) & 1) * 16;           // A: mats 2,3 -> k+8
    const uint32_t bK16 = ((lane >> 3) & 1) * 16;           // B: mats 1,3 -> k+8
    const int aRowL = (lane & 15);                          // A row within m16
    const int bRowL = (lane & 7) + ((lane >> 4) & 1) * 8;   // B row within n16
    uint32_t aOff[2], bOff[4];
#pragma unroll
    for (int mi = 0; mi < 2; mi++)
        aOff[mi] = (uint32_t)(wm * 32 + mi * 16 + aRowL) * 128;
#pragma unroll
    for (int g = 0; g < 4; g++)
        bOff[g] = (uint32_t)(wn * 64 + g * 16 + bRowL) * 128;

    auto load_stage = [&](int kt, int s) {
        const int k0 = kt << 6;
        const uint32_t sA = sbase + (uint32_t)s * 32768u;
        const uint32_t sB = sA + 16384u;
#pragma unroll
        for (int i = 0; i < 4; i++) {                 // A: 128 rows x 8 chunks
            const int idx = tid + i * 256;
            const int row = idx >> 3, c = idx & 7;
            cp16(sA + (uint32_t)(row * 128) + (uint32_t)((c ^ (row & 7)) << 4),
                 A + (size_t)(m0 + row) * KK + k0 + c * 8);
        }
#pragma unroll
        for (int i = 0; i < 4; i++) {                 // B: 128 rows x 8 chunks
            const int idx = tid + i * 256;
            const int row = idx >> 3, c = idx & 7;
            cp16(sB + (uint32_t)(row * 128) + (uint32_t)((c ^ (row & 7)) << 4),
                 Bm + (size_t)(n0 + row) * KK + k0 + c * 8);
        }
        asm volatile("cp.async.commit_group;");
    };

    load_stage(0, 0);

    for (int kt = 0; kt < 16; ++kt) {
        const int cur = kt & 1;
        if (kt < 15) {
            load_stage(kt + 1, cur ^ 1);              // issue BEFORE wait (R7)
            asm volatile("cp.async.wait_group 1;");
        } else {
            asm volatile("cp.async.wait_group 0;");
        }
        __syncthreads();

        const uint32_t sA = sbase + (uint32_t)cur * 32768u;
        const uint32_t sB = sA + 16384u;
#pragma unroll
        for (int kk = 0; kk < 4; ++kk) {
            uint32_t a[2][4], b[4][4];
#pragma unroll
            for (int mi = 0; mi < 2; mi++)
                LDSM4(a[mi], sA + aOff[mi] + (((uint32_t)(kk * 32) + aK16) ^ sw));
#pragma unroll
            for (int g = 0; g < 4; g++)
                LDSM4(b[g], sB + bOff[g] + (((uint32_t)(kk * 32) + bK16) ^ sw));
#pragma unroll
            for (int mi = 0; mi < 2; mi++)
#pragma unroll
                for (int ni = 0; ni < 8; ni++)
                    mma16(acc[mi][ni], a[mi],
                          b[ni >> 1][(ni & 1) * 2], b[ni >> 1][(ni & 1) * 2 + 1]);
        }
        __syncthreads();
    }

    // epilogue (direct stores)
    const int r  = lane >> 2;
    const int cq = lane & 3;
#pragma unroll
    for (int mi = 0; mi < 2; mi++) {
#pragma unroll
        for (int ni = 0; ni < 8; ni++) {
            const int colb = n0 + wn * 64 + ni * 8 + (cq << 1);
            float bias0 = 0.f, bias1 = 0.f;
            if (MODE != 0 || colb < PP)     bias0 = __ldg(bias + colb);
            if (MODE != 0 || colb + 1 < PP) bias1 = __ldg(bias + colb + 1);
#pragma unroll
            for (int cr = 0; cr < 4; cr++) {
                const int row = m0 + wm * 32 + mi * 16 + r + ((cr >> 1) << 3);
                const int col = colb + (cr & 1);
                float v = acc[mi][ni][cr] + ((cr & 1) ? bias1 : bias0);
                if (MODE == 0) {
                    if (col < PP) {
                        if (col < DD)
                            g_query[(size_t)row * DD + col] = v;
                        else if (col < 2 * DD)
                            g_ctx[(size_t)row * DD + (col - DD)] = v;
                        else
                            g_gates[(size_t)row * 3 + (col - 2 * DD)] = v;
                    }
                } else if (MODE == 1) {
                    v *= __ldg(&g_query[(size_t)row * DD + col]);
                    g_yh[(size_t)row * DD + col] = __float2half_rn(v);
                } else {
                    Cout[(size_t)row * DD + col] = v;
                }
            }
        }
    }
}

// ---------------- depthwise conv chain (k=14 then k=18) ----------------------
// Register sliding-window: contiguous run of outputs per thread.
__global__ void __launch_bounds__(256)
conv_kernel(const float* __restrict__ w0p, const float* __restrict__ b0p,
            const float* __restrict__ w1p, const float* __restrict__ b1p) {
    __shared__ float xs[158 * 32];   // ctx tile: s = s0-14 .. s0+143
    __shared__ float c0s[146 * 32];  // c0 tile:  u = s0-8  .. s0+136

    const int tid = threadIdx.x;
    const int d = tid & 31, chunk = tid >> 5;
    const int b = blockIdx.z, d0 = blockIdx.y << 5, s0 = blockIdx.x << 7;
    const int dg = d0 + d;

    float W0[14], W1[18];
#pragma unroll
    for (int i = 0; i < 14; i++) W0[i] = __ldg(w0p + dg * 14 + i);
#pragma unroll
    for (int i = 0; i < 18; i++) W1[i] = __ldg(w1p + dg * 18 + i);
    const float B0 = __ldg(b0p + dg);
    const float B1 = __ldg(b1p + dg);

    {
        const float* ctxb = g_ctx + (size_t)b * SS_ * DD + d0;
        for (int idx = tid; idx < 158 * 8; idx += 256) {
            const int sl = idx >> 3, q = idx & 7;
            const int s = s0 - 14 + sl;
            float4 v = make_float4(0.f, 0.f, 0.f, 0.f);
            if (s >= 0 && s < SS_)
                v = *(const float4*)(ctxb + (size_t)s * DD + q * 4);
            *(float4*)(&xs[sl * 32 + q * 4]) = v;
        }
    }
    __syncthreads();

    // c0 phase: 145 outputs, contiguous runs of 19/thread
    {
        const int ul0 = chunk * 19;
        const int cnt = min(19, 145 - ul0);
        float w[14];
#pragma unroll
        for (int j = 0; j < 14; j++) w[j] = xs[(ul0 + j) * 32 + d];
#pragma unroll
        for (int it = 0; it < 19; ++it) {
            if (it < cnt) {
                float a = B0;
#pragma unroll
                for (int i = 0; i < 14; i++) a += w[(it + i) % 14] * W0[i];
                const int u = s0 - 8 + ul0 + it;
                c0s[(ul0 + it) * 32 + d] = (u >= 0 && u < SS_) ? gelu_f(a) : 0.0f;
                if (it + 1 < cnt)
                    w[it % 14] = xs[(ul0 + it + 14) * 32 + d];
            }
        }
    }
    __syncthreads();

    // c1 phase: 128 outputs, contiguous runs of 16/thread
    float csum = 0.0f;
    {
        const int tl0 = chunk * 16;
        float w[18];
#pragma unroll
        for (int j = 0; j < 18; j++) w[j] = c0s[(tl0 + j) * 32 + d];
#pragma unroll
        for (int it = 0; it < 16; ++it) {
            float a = B1;
#pragma unroll
            for (int i = 0; i < 18; i++) a += w[(it + i) % 18] * W1[i];
            const float c1 = gelu_f(a);
            csum += c1;
            const int t = s0 + tl0 + it;
            const size_t ms = (size_t)b * SS_ + t;
            const float g0v = __ldg(&g_gates[ms * 3 + 0]);
            const float g1v = __ldg(&g_gates[ms * 3 + 1]);
            const float c0c = w[(it + 8) % 18];
            g_ca[ms * DD + dg] = c0c * g0v + c1 * g1v;
            if (it + 1 < 16)
                w[it % 18] = c0s[(tl0 + it + 18) * 32 + d];
        }
    }
    __syncthreads();
    xs[chunk * 32 + d] = csum;
    __syncthreads();
    if (chunk == 0) {
        float s_ = 0.0f;
#pragma unroll
        for (int j = 0; j < 8; j++) s_ += xs[j * 32 + d];
        g_c1part[((size_t)b * DD + dg) * 32 + blockIdx.x] = s_;
    }
}

__global__ void gmean_kernel() {
    const int i = blockIdx.x * blockDim.x + threadIdx.x;
    if (i < BB * DD) {
        float s = 0.0f;
        const float* p = &g_c1part[(size_t)i * 32];
#pragma unroll
        for (int j = 0; j < 32; j++) s += p[j];
        g_g[i] = gelu_f(s * (1.0f / 4096.0f));
    }
}

// cah = half(ca + g*gates2)
__global__ void finalize_kernel() {
    const size_t i = (size_t)blockIdx.x * blockDim.x + threadIdx.x;
    const int d4 = (int)(i & 255);
    const size_t ms = i >> 8;
    const int b = (int)(ms >> 12);
    const float g2 = __ldg(&g_gates[ms * 3 + 2]);
    const float4 gv = ((const float4*)g_g)[(size_t)b * 256 + d4];
    float4 c = ((const float4*)g_ca)[i];
    c.x = fmaf(gv.x, g2, c.x);
    c.y = fmaf(gv.y, g2, c.y);
    c.z = fmaf(gv.z, g2, c.z);
    c.w = fmaf(gv.w, g2, c.w);
    ((__half2*)g_cah)[2 * i]     = __floats2half2_rn(c.x, c.y);
    ((__half2*)g_cah)[2 * i + 1] = __floats2half2_rn(c.z, c.w);
}

// ---------------- launch -----------------------------------------------------
extern "C" void kernel_launch(void* const* d_in, const int* in_sizes, int n_in,
                              void* d_out, int out_size) {
    (void)in_sizes; (void)n_in; (void)out_size;
    const float* input = (const float*)d_in[0];
    const float* W_in  = (const float*)d_in[1];
    const float* b_in  = (const float*)d_in[2];
    const float* w0    = (const float*)d_in[3];
    const float* b0    = (const float*)d_in[4];
    const float* w1    = (const float*)d_in[5];
    const float* b1    = (const float*)d_in[6];
    const float* W_ctx = (const float*)d_in[7];
    const float* b_ctx = (const float*)d_in[8];
    const float* W_out = (const float*)d_in[9];
    const float* b_out = (const float*)d_in[10];
    float* out = (float*)d_out;

    void *pAh = nullptr, *pB1 = nullptr, *pB2 = nullptr, *pB3 = nullptr,
         *pCa = nullptr, *pY = nullptr;
    cudaGetSymbolAddress(&pAh, g_Ah);
    cudaGetSymbolAddress(&pB1, g_B1h);
    cudaGetSymbolAddress(&pB2, g_B2h);
    cudaGetSymbolAddress(&pB3, g_B3h);
    cudaGetSymbolAddress(&pCa, g_cah);
    cudaGetSymbolAddress(&pY, g_yh);

    const int GSMEM = 65536;   // 2 stages x 32KB -> 2 CTAs/SM
    cudaFuncSetAttribute(gemm_fp16<0>, cudaFuncAttributeMaxDynamicSharedMemorySize, GSMEM);
    cudaFuncSetAttribute(gemm_fp16<1>, cudaFuncAttributeMaxDynamicSharedMemorySize, GSMEM);
    cudaFuncSetAttribute(gemm_fp16<2>, cudaFuncAttributeMaxDynamicSharedMemorySize, GSMEM);

    // 0-2: operand prep needed by GEMM1
    cvtA_kernel<<<(MM * KK / 4 + 255) / 256, 256>>>(input, MM * KK / 4);
    prep_b1h_kernel<<<dim3(68, 32), dim3(32, 8)>>>(W_in);
    prep_b2h_kernel<<<(DD * KK / 4 + 255) / 256, 256>>>(W_ctx, DD * KK / 4);
    // 3: GEMM1
    gemm_fp16<0><<<dim3(17, 256), 256, GSMEM>>>((const __half*)pAh, (const __half*)pB1,
                                                b_in, nullptr);
    // 4: remaining prep
    prep_b3h_kernel<<<dim3(32, 32), dim3(32, 8)>>>(W_out);
    // 5: conv chain -> ca + c1 partial sums
    conv_kernel<<<dim3(32, 32, 8), 256>>>(w0, b0, w1, b1);
    // 6: g = gelu(mean c1)
    gmean_kernel<<<32, 256>>>();
    // 7: cah = half(ca + g*gates2)
    finalize_kernel<<<32768, 256>>>();
    // 8: GEMM2: yh = half((cah @ W_ctx^T + b_ctx) * query)
    gemm_fp16<1><<<dim3(8, 256), 256, GSMEM>>>((const __half*)pCa, (const __half*)pB2,
                                               b_ctx, nullptr);
    // 9: GEMM3: out = yh @ W_out + b_out
    gemm_fp16<2><<<dim3(8, 256), 256, GSMEM>>>((const __half*)pY, (const __half*)pB3,
                                               b_out, out);
}